// round 6
// baseline (speedup 1.0000x reference)
#include <cuda_runtime.h>
#include <cuda_bf16.h>
#include <cstdint>

// Locally-connected 2D via mma.sync m16n8k16 bf16, 3-pass hi/lo split.
//   out[b,o,y,x] = sum_k patches[b,y,x,k] * W[y,x,o,k] + bias[y,x,o]
// x: [128,3,64,64] f32, W: [60,60,32,75] f32 (k = c*25+kh*5+kw),
// bias: [60,60,32] f32, out: [128,32,60,60] f32.
// Per position: D[128x32] = A[128x75] @ B[75x32].
// W is pre-split (hi/lo bf16) and pre-swizzled into the HMMA fragment layout
// by prep_w_kernel; x pre-packed (bf16hi<<16|bf16lo) by prep_x_kernel.

#define RYX  60
#define TX   4        // positions per CTA
#define XC   8        // x cols staged (TX + 4)
#define SXB  132      // sXp row stride (u32)
#define WROW 44       // W o-row stride (u32 pairs)
#define WPOS 1408     // u32 per (pos, hi|lo) array: 32*44

// ---- smem layout (bytes) ----
#define XP_BYTES   (120 * SXB * 4)                 // 63360
#define WHI_OFF    XP_BYTES
#define WLO_OFF    (WHI_OFF + TX * 32 * WROW * 4)  // +22528
#define BIAS_OFF   (WLO_OFF + TX * 32 * WROW * 4)  // +22528
#define SMEM_TOTAL (BIAS_OFF + 512)                // 108928

__device__ unsigned g_xp[3 * 64 * 64 * 128];           // packed x
__device__ unsigned g_wfrag[3600 * 2 * WPOS];          // [pos][hi|lo][32][44]

// ---------------------------------------------------------------- helpers
__device__ __forceinline__ unsigned smem_u32(const void* p) {
    unsigned a;
    asm("{ .reg .u64 t; cvta.to.shared.u64 t, %1; cvt.u32.u64 %0, t; }" : "=r"(a) : "l"(p));
    return a;
}
__device__ __forceinline__ void cp16(unsigned sm, const void* g) {
    asm volatile("cp.async.cg.shared.global [%0], [%1], 16;"
                 :: "r"(sm), "l"(__cvta_generic_to_global(g)) : "memory");
}
__device__ __forceinline__ void cp_commit_wait() {
    asm volatile("cp.async.commit_group;" ::: "memory");
    asm volatile("cp.async.wait_group 0;" ::: "memory");
}
__device__ __forceinline__ int rcof(int k) {       // smem row for flat k (pos 0)
    int c = k / 25, r = (k % 25) / 5, w = k % 5;
    return (c * 5 + r) * 8 + w;
}
__device__ __forceinline__ void mma_bf16(float* d, const unsigned* a, unsigned b0, unsigned b1) {
    asm volatile(
        "mma.sync.aligned.m16n8k16.row.col.f32.bf16.bf16.f32 "
        "{%0,%1,%2,%3}, {%4,%5,%6,%7}, {%8,%9}, {%0,%1,%2,%3};"
        : "+f"(d[0]), "+f"(d[1]), "+f"(d[2]), "+f"(d[3])
        : "r"(a[0]), "r"(a[1]), "r"(a[2]), "r"(a[3]), "r"(b0), "r"(b1));
}

// ---------------------------------------------------------------- prep: pack x
__global__ __launch_bounds__(256)
void prep_x_kernel(const float* __restrict__ x)
{
    __shared__ unsigned tile[32][33];
    const int wt    = blockIdx.x & 1;
    const int btile = blockIdx.x >> 1;
    const int h     = blockIdx.y;
    const int c     = blockIdx.z;
    const int tx = threadIdx.x, ty = threadIdx.y;

    #pragma unroll
    for (int j = 0; j < 4; j++) {
        int b = btile * 32 + ty + j * 8;
        float v = x[(((size_t)b * 3 + c) * 64 + h) * 64 + wt * 32 + tx];
        __nv_bfloat16 hi = __float2bfloat16_rn(v);
        __nv_bfloat16 lo = __float2bfloat16_rn(v - __bfloat162float(hi));
        tile[ty + j * 8][tx] = ((unsigned)__bfloat16_as_ushort(hi) << 16)
                             |  (unsigned)__bfloat16_as_ushort(lo);
    }
    __syncthreads();
    #pragma unroll
    for (int j = 0; j < 4; j++) {
        int w = wt * 32 + ty + j * 8;
        g_xp[(((size_t)c * 64 + h) * 64 + w) * 128 + btile * 32 + tx] = tile[tx][ty + j * 8];
    }
}

// ---------------------------------------------------------------- prep: split W
// Writes the exact smem fragment image: u32[o*44 + s*8 + f] = bf16(k)|bf16(k+1)<<16
// where kp = s*8 + jj, jj = (f>>1)|((f&1)<<2), k = 2*kp.  (hi array, then lo.)
__global__ __launch_bounds__(256)
void prep_w_kernel(const float* __restrict__ W)
{
    const int pos = blockIdx.x;
    const float* Wg = W + (size_t)pos * (32 * 75);
    unsigned* dhi = g_wfrag + (size_t)pos * (2 * WPOS);
    unsigned* dlo = dhi + WPOS;

    for (int i = threadIdx.x; i < 32 * 40; i += 256) {
        int o  = i / 40;
        int j0 = i - o * 40;               // s*8 + f
        int f  = j0 & 7;
        int jj = (f >> 1) | ((f & 1) << 2);
        int k  = 2 * ((j0 & ~7) + jj);     // 2*(s*8 + jj)

        float v0 = (k     < 75) ? Wg[o * 75 + k]     : 0.0f;
        float v1 = (k + 1 < 75) ? Wg[o * 75 + k + 1] : 0.0f;

        unsigned w0 = __float_as_uint(v0), w1 = __float_as_uint(v1);
        unsigned h0 = w0 >> 16, h1 = w1 >> 16;
        float l0f = v0 - __uint_as_float(w0 & 0xFFFF0000u);
        float l1f = v1 - __uint_as_float(w1 & 0xFFFF0000u);
        unsigned l0 = __bfloat16_as_ushort(__float2bfloat16_rn(l0f));
        unsigned l1 = __bfloat16_as_ushort(__float2bfloat16_rn(l1f));

        dhi[o * WROW + j0] = h0 | (h1 << 16);
        dlo[o * WROW + j0] = l0 | (l1 << 16);
    }
}

// ---------------------------------------------------------------- main
__global__ __launch_bounds__(256, 2)
void lc2d_hmma_kernel(const float* __restrict__ bias,
                      float* __restrict__ out)
{
    extern __shared__ char smem[];
    unsigned* sXp   = (unsigned*)smem;              // [120 rc][SXB] packed u32
    unsigned* sWhi  = (unsigned*)(smem + WHI_OFF);  // [TX*32][WROW]
    unsigned* sWlo  = (unsigned*)(smem + WLO_OFF);
    float*    sBias = (float*)(smem + BIAS_OFF);    // [TX][32]

    const int xt   = blockIdx.x;          // 15
    const int py   = blockIdx.y;          // 60
    const int px0  = xt * TX;
    const int pos0 = py * RYX + px0;
    const int tid  = threadIdx.x;

    const unsigned sXp_a  = smem_u32(sXp);
    const unsigned sWhi_a = smem_u32(sWhi);
    const unsigned sWlo_a = smem_u32(sWlo);

    // ---- stage x tile: cp.async uint4, coalesced ----
    for (int i = tid; i < 120 * 32; i += 256) {
        int q    = i & 31;
        int rc   = i >> 5;                 // (c*5+kh)*8 + col
        int crow = rc >> 3, col = rc & 7;
        int c = crow / 5, kh = crow - c * 5;
        cp16(sXp_a + (rc * SXB + q * 4) * 4,
             &g_xp[(((size_t)c * 64 + py + kh) * 64 + px0 + col) * 128 + q * 4]);
    }

    // ---- stage W fragments: pure contiguous copy (4 pos x 2 arrays x 1408 u32) ----
    {
        const unsigned* src = g_wfrag + (size_t)pos0 * (2 * WPOS);
        for (int i = tid; i < 2 * TX * (WPOS / 4); i += 256) {   // 2816 uint4
            int p = i / (2 * (WPOS / 4));
            int r = i - p * (2 * (WPOS / 4));
            int a = r / (WPOS / 4);
            int j = r - a * (WPOS / 4);
            unsigned dst = (a ? sWlo_a : sWhi_a) + (p * WPOS + j * 4) * 4;
            cp16(dst, src + (size_t)p * (2 * WPOS) + a * WPOS + j * 4);
        }
    }
    if (tid < TX * 32) sBias[tid] = bias[pos0 * 32 + tid];
    cp_commit_wait();
    __syncthreads();

    // ---- compute: warp = (position p, m-half mh); 4 m-tiles x 4 n-tiles ----
    const int wid  = tid >> 5;
    const int lane = tid & 31;
    const int gid  = lane >> 2;
    const int tg   = lane & 3;
    const int p    = wid >> 1;
    const int mh   = wid & 1;

    float acc[4][4][4];
    #pragma unroll
    for (int mt = 0; mt < 4; mt++)
        #pragma unroll
        for (int nt = 0; nt < 4; nt++)
            #pragma unroll
            for (int r = 0; r < 4; r++) acc[mt][nt][r] = 0.0f;

    const unsigned* wh = sWhi + (p * 32 + gid) * WROW + 2 * tg;
    const unsigned* wl = sWlo + (p * 32 + gid) * WROW + 2 * tg;

    #pragma unroll
    for (int s = 0; s < 5; s++) {
        // B fragments: 4 n-tiles, hi+lo, one uint2 each
        unsigned bh[4][2], bl[4][2];
        #pragma unroll
        for (int nt = 0; nt < 4; nt++) {
            uint2 h = *reinterpret_cast<const uint2*>(wh + nt * 8 * WROW + s * 8);
            uint2 l = *reinterpret_cast<const uint2*>(wl + nt * 8 * WROW + s * 8);
            bh[nt][0] = h.x; bh[nt][1] = h.y;
            bl[nt][0] = l.x; bl[nt][1] = l.y;
        }

        // A row offsets for k0, k0+1, k0+8, k0+9
        const int k0 = 16 * s + 2 * tg;
        int off0, off1, off2, off3;
        bool v2 = true, v3 = true;
        if (s < 4) {
            off0 = (rcof(k0)     + p) * SXB;
            off1 = (rcof(k0 + 1) + p) * SXB;
            off2 = (rcof(k0 + 8) + p) * SXB;
            off3 = (rcof(k0 + 9) + p) * SXB;
        } else {
            off0 = (rcof(k0)     + p) * SXB;
            off1 = (rcof(k0 + 1) + p) * SXB;
            v2 = (k0 + 8) < 75;  off2 = v2 ? (rcof(k0 + 8) + p) * SXB : 0;
            v3 = (k0 + 9) < 75;  off3 = v3 ? (rcof(k0 + 9) + p) * SXB : 0;
        }

        #pragma unroll
        for (int mt = 0; mt < 4; mt++) {
            const int b = mh * 64 + mt * 16 + gid;
            unsigned x0 = sXp[off0 + b];
            unsigned x1 = sXp[off1 + b];
            unsigned x2 = sXp[off0 + b + 8];
            unsigned x3 = sXp[off1 + b + 8];
            unsigned x4 = v2 ? sXp[off2 + b]     : 0u;
            unsigned x5 = v3 ? sXp[off3 + b]     : 0u;
            unsigned x6 = v2 ? sXp[off2 + b + 8] : 0u;
            unsigned x7 = v3 ? sXp[off3 + b + 8] : 0u;

            unsigned ah[4], al[4];
            ah[0] = __byte_perm(x0, x1, 0x7632);  al[0] = __byte_perm(x0, x1, 0x5410);
            ah[1] = __byte_perm(x2, x3, 0x7632);  al[1] = __byte_perm(x2, x3, 0x5410);
            ah[2] = __byte_perm(x4, x5, 0x7632);  al[2] = __byte_perm(x4, x5, 0x5410);
            ah[3] = __byte_perm(x6, x7, 0x7632);  al[3] = __byte_perm(x6, x7, 0x5410);

            #pragma unroll
            for (int nt = 0; nt < 4; nt++) {
                mma_bf16(acc[mt][nt], ah, bh[nt][0], bh[nt][1]);   // hi*hi
                mma_bf16(acc[mt][nt], ah, bl[nt][0], bl[nt][1]);   // hi*lo
                mma_bf16(acc[mt][nt], al, bh[nt][0], bh[nt][1]);   // lo*hi
            }
        }
    }

    // ---- repack: sRep[px][b][o-pair] float2 (overlay, inputs dead) ----
    __syncthreads();
    float2* sRep = (float2*)smem;        // [(p*128 + b)*17 + nt*4 + tg]
    #pragma unroll
    for (int mt = 0; mt < 4; mt++) {
        #pragma unroll
        for (int rh = 0; rh < 2; rh++) {
            const int b = mh * 64 + mt * 16 + gid + rh * 8;
            #pragma unroll
            for (int nt = 0; nt < 4; nt++) {
                sRep[(p * 128 + b) * 17 + nt * 4 + tg] =
                    make_float2(acc[mt][nt][rh * 2], acc[mt][nt][rh * 2 + 1]);
            }
        }
    }
    __syncthreads();

    // ---- store: float4 over px (16B contiguous) ----
    const float* rf = (const float*)smem;
    for (int j = tid; j < 128 * 32; j += 256) {
        int b = j >> 5, o = j & 31;
        float4 v;
        v.x = rf[((0 * 128 + b) * 34) + o] + sBias[0 * 32 + o];
        v.y = rf[((1 * 128 + b) * 34) + o] + sBias[1 * 32 + o];
        v.z = rf[((2 * 128 + b) * 34) + o] + sBias[2 * 32 + o];
        v.w = rf[((3 * 128 + b) * 34) + o] + sBias[3 * 32 + o];
        *reinterpret_cast<float4*>(&out[((size_t)(b * 32 + o)) * 3600 + pos0]) = v;
    }
}

// ---------------------------------------------------------------- launch
extern "C" void kernel_launch(void* const* d_in, const int* in_sizes, int n_in,
                              void* d_out, int out_size)
{
    const float* x    = (const float*)d_in[0];
    const float* W    = (const float*)d_in[1];
    const float* bias = (const float*)d_in[2];
    float* out        = (float*)d_out;

    cudaFuncSetAttribute(lc2d_hmma_kernel,
                         cudaFuncAttributeMaxDynamicSharedMemorySize, SMEM_TOTAL);

    prep_x_kernel<<<dim3(8, 64, 3), dim3(32, 8)>>>(x);
    prep_w_kernel<<<3600, 256>>>(W);
    lc2d_hmma_kernel<<<dim3(RYX / TX, RYX), 256, SMEM_TOTAL>>>(bias, out);
}